// round 10
// baseline (speedup 1.0000x reference)
#include <cuda_runtime.h>
#include <cuda_fp16.h>
#include <cstdint>
#include <math.h>

#define BS 16
#define C  64
#define H  128
#define W  128
#define EXP 4
#define HID 16

// ---------------- static device scratch ----------------
__device__ float g_rowsum[BS * C * H];     // [b][c][y]
__device__ float g_pooled[BS * C];
__device__ float g_coeff[BS * C * EXP];
__device__ float g_ab[3 * BS * C];
// pre-mixed fp16 weights: [layer][b][ky][kx][o=64][ci=64]
__device__ __align__(16) __half g_wB[3 * BS * 3 * 3 * 64 * 64];
// NHWC fp16 ping-pong activation planes: [b][y][x][ci]
__device__ __align__(16) __half g_a0[BS * H * W * C];
__device__ __align__(16) __half g_a1[BS * H * W * C];

// ---------------- helpers ----------------
__device__ __forceinline__ uint32_t smem_u32(const void* p) {
    uint32_t a;
    asm("{ .reg .u64 t; cvta.to.shared.u64 t, %1; cvt.u32.u64 %0, t; }" : "=r"(a) : "l"(p));
    return a;
}
__device__ __forceinline__ void ldsm4(uint32_t* r, uint32_t addr) {
    asm volatile("ldmatrix.sync.aligned.m8n8.x4.shared.b16 {%0,%1,%2,%3}, [%4];"
        : "=r"(r[0]), "=r"(r[1]), "=r"(r[2]), "=r"(r[3]) : "r"(addr));
}
__device__ __forceinline__ void mma16816(float* c, const uint32_t* a, uint32_t b0, uint32_t b1) {
    asm volatile("mma.sync.aligned.m16n8k16.row.col.f32.f16.f16.f32 "
        "{%0,%1,%2,%3}, {%4,%5,%6,%7}, {%8,%9}, {%0,%1,%2,%3};"
        : "+f"(c[0]), "+f"(c[1]), "+f"(c[2]), "+f"(c[3])
        : "r"(a[0]), "r"(a[1]), "r"(a[2]), "r"(a[3]), "r"(b0), "r"(b1));
}
#define CP16(dst, src, sz) \
    asm volatile("cp.async.cg.shared.global [%0], [%1], 16, %2;" \
        :: "r"(dst), "l"(src), "r"(sz) : "memory")
#define CP_COMMIT() \
    asm volatile("cp.async.commit_group;" ::: "memory")
#define CP_WAIT0() \
    asm volatile("cp.async.wait_group 0;" ::: "memory")
#define CP_COMMIT_WAIT() \
    asm volatile("cp.async.commit_group;\n\tcp.async.wait_group 0;" ::: "memory")

// ---------------- kernel D: NCHW fp32 -> NHWC fp16 (+ per-row channel sums) ----------------
__global__ void xsplit_kernel(const float* __restrict__ x, __half* __restrict__ oh) {
    int y = blockIdx.x, b = blockIdx.y;
    __shared__ float sm[64][129];
    for (int i = threadIdx.x; i < 64 * 128; i += 256) {
        int ci = i >> 7, xx = i & 127;
        sm[ci][xx] = x[(((size_t)b * C + ci) * H + y) * W + xx];
    }
    __syncthreads();
    // per-row channel sums: 4 threads per channel
    {
        int c = threadIdx.x >> 2, q = threadIdx.x & 3;
        float s = 0.f;
        #pragma unroll
        for (int i = 0; i < 32; i++) s += sm[c][q * 32 + i];
        s += __shfl_xor_sync(0xFFFFFFFF, s, 1);
        s += __shfl_xor_sync(0xFFFFFFFF, s, 2);
        if (q == 0) g_rowsum[((size_t)b * C + c) * H + y] = s;
    }
    int xx = threadIdx.x & 127;
    int half_ = threadIdx.x >> 7;
    size_t base = (((size_t)b * H + y) * W + xx) * C + half_ * 32;
    uint32_t hb[16];
    #pragma unroll
    for (int c = 0; c < 32; c += 2) {
        __half2 p = __floats2half2_rn(sm[half_ * 32 + c][xx], sm[half_ * 32 + c + 1][xx]);
        hb[c >> 1] = *(uint32_t*)&p;
    }
    #pragma unroll
    for (int q = 0; q < 4; q++)
        ((uint4*)(oh + base))[q] = ((uint4*)hb)[q];
}

// ---------------- kernel A2: reduce row sums -> pooled mean ----------------
__global__ void pool2_kernel() {
    int bc = blockIdx.x * 256 + threadIdx.x;     // 0..1023
    if (bc >= BS * C) return;
    const float4* p = (const float4*)&g_rowsum[(size_t)bc * H];
    float s = 0.f;
    #pragma unroll
    for (int i = 0; i < H / 4; i++) {
        float4 v = p[i];
        s += (v.x + v.y) + (v.z + v.w);
    }
    g_pooled[bc] = s * (1.0f / (H * W));
}

// ---------------- kernel B: control MLP + softmax + bias mixing ----------------
__global__ void ctrl_kernel(const float* __restrict__ w1, const float* __restrict__ w2,
                            const float* __restrict__ b1, const float* __restrict__ b2,
                            const float* __restrict__ b3) {
    __shared__ float sp[BS * C];
    __shared__ float sh[BS * HID];
    __shared__ float sl[BS * EXP * C];
    int t = threadIdx.x;
    for (int i = t; i < BS * C; i += 256) sp[i] = g_pooled[i];
    __syncthreads();
    {
        int b = t / HID, hh = t % HID;
        float s = 0.f;
        #pragma unroll 8
        for (int c = 0; c < C; c++) s += sp[b * C + c] * w1[hh * C + c];
        sh[b * HID + hh] = fmaxf(s, 0.f);
    }
    __syncthreads();
    for (int b = 0; b < BS; b++) {
        float s = 0.f;
        #pragma unroll
        for (int h = 0; h < HID; h++) s += sh[b * HID + h] * w2[t * HID + h];
        sl[b * (EXP * C) + t] = s;
    }
    __syncthreads();
    for (int g = t; g < BS * C; g += 256) {
        int b = g / C, c = g % C;
        float v[EXP];
        float mx = -1e30f;
        #pragma unroll
        for (int e = 0; e < EXP; e++) {
            v[e] = sl[b * (EXP * C) + c * EXP + e] * (1.0f / 30.0f);
            mx = fmaxf(mx, v[e]);
        }
        float den = 0.f;
        #pragma unroll
        for (int e = 0; e < EXP; e++) { v[e] = expf(v[e] - mx); den += v[e]; }
        float inv = 1.0f / den;
        #pragma unroll
        for (int e = 0; e < EXP; e++) g_coeff[g * EXP + e] = v[e] * inv;
    }
    __syncthreads();
    for (int g = t; g < BS * C; g += 256) {
        int c = g % C;
        float c0 = g_coeff[g * EXP + 0], c1 = g_coeff[g * EXP + 1];
        float c2 = g_coeff[g * EXP + 2], c3 = g_coeff[g * EXP + 3];
        g_ab[0 * BS * C + g] = c0 * b1[c] + c1 * b1[C + c] + c2 * b1[2 * C + c] + c3 * b1[3 * C + c];
        g_ab[1 * BS * C + g] = c0 * b2[c] + c1 * b2[C + c] + c2 * b2[2 * C + c] + c3 * b2[3 * C + c];
        g_ab[2 * BS * C + g] = c0 * b3[c] + c1 * b3[C + c] + c2 * b3[2 * C + c] + c3 * b3[3 * C + c];
    }
}

// ---------------- kernel C: mix weights -> fp16 ----------------
__global__ void mixsplit_kernel(const float* __restrict__ W1, const float* __restrict__ W2,
                                const float* __restrict__ W3) {
    int b = blockIdx.x, layer = blockIdx.y;
    const float* Wt = (layer == 0) ? W1 : (layer == 1) ? W2 : W3;
    __half* base = g_wB + ((size_t)(layer * BS + b)) * 3 * 3 * 4096;
    const float* cfb = &g_coeff[b * C * EXP];
    const size_t eb = (size_t)C * C * 9;
    for (int idx = threadIdx.x; idx < 64 * 64 * 9; idx += 256) {
        int kk = idx % 9;
        int ci = (idx / 9) % 64;
        int o  = idx / (9 * 64);
        int ky = kk / 3, kx = kk % 3;
        float c0 = cfb[o * EXP + 0], c1 = cfb[o * EXP + 1];
        float c2 = cfb[o * EXP + 2], c3 = cfb[o * EXP + 3];
        size_t w0 = (((size_t)o) * C + ci) * 9 + kk;
        float v = c0 * Wt[w0] + c1 * Wt[eb + w0] + c2 * Wt[2 * eb + w0] + c3 * Wt[3 * eb + w0];
        base[((size_t)ky * 3 + kx) * 4096 + o * 64 + ci] = __float2half_rn(v);
    }
}

// ---------------- kernel E: mma.sync fp16 conv, 4-slot A prologue ----------------
// smem: A = 4 slots x [130px x 128B] = 66560; B = 2 bufs x [kx(3) x 8192] = 49152
#define SA_SLOT 16640
#define SB_OFF  66560
#define SB_BUF  24576
#define SMEM_TOTAL (SB_OFF + 2 * SB_BUF)

__global__ void __launch_bounds__(256, 2)
conv_mma_kernel(const __half* __restrict__ in_a,
                const __half* __restrict__ wb,     // layer base: [b][ky][kx][64][64]
                const float* __restrict__ ab,      // [b][64]
                float* __restrict__ out_f32,
                __half* __restrict__ out_a,
                int final_layer) {
    extern __shared__ __align__(16) unsigned char smem[];
    const uint32_t sbase = smem_u32(smem);
    const int tid  = threadIdx.x;
    const int y0   = blockIdx.x * 2;
    const int b    = blockIdx.y;
    const int lane = tid & 31;
    const int w    = tid >> 5;
    const int m0   = w * 16;

    const int rA  = lane & 15;
    const int khA = lane >> 4;
    const int rn  = lane & 7;
    const int khB = (lane >> 3) & 1;
    const int qn  = lane >> 4;

    float acc[2][8][4];
    #pragma unroll
    for (int r = 0; r < 2; r++)
        #pragma unroll
        for (int j = 0; j < 8; j++)
            #pragma unroll
            for (int q = 0; q < 4; q++) acc[r][j][q] = 0.f;

    const __half* wbb = wb + (size_t)b * (3 * 3 * 4096);

    auto stage_A = [&](int gy, int slot) {
        const int gy_ok = (gy >= 0 && gy < H);
        const size_t rowbase = ((size_t)(b * H + (gy_ok ? gy : 0)) * W) * C;
        const uint32_t slotbase = sbase + slot * SA_SLOT;
        for (int i = tid; i < 1040; i += 256) {
            int px = i >> 3, c = i & 7;
            int gx = px - 1;
            int ok = gy_ok && (gx >= 0) && (gx < W);
            const __half* sp = in_a + rowbase + (size_t)(ok ? gx : 0) * C + c * 8;
            uint32_t dst = slotbase + px * 128 + (((uint32_t)(c ^ (px & 7))) << 4);
            CP16(dst, sp, ok ? 16 : 0);
        }
    };
    auto stage_B = [&](int ky, int buf) {
        const __half* wk = wbb + (size_t)ky * (3 * 4096);
        for (int i = tid; i < 1536; i += 256) {
            int c = i & 7;
            int n = (i >> 3) & 63;
            int kx = i >> 9;
            const __half* sp = wk + (size_t)kx * 4096 + n * 64 + c * 8;
            uint32_t dst = sbase + SB_OFF + buf * SB_BUF + kx * 8192 + n * 128
                           + (((uint32_t)(c ^ (n & 7))) << 4);
            CP16(dst, sp, 16);
        }
    };

    // prologue: ALL four A rows + B(ky=0)
    stage_A(y0 - 1, 0);
    stage_A(y0,     1);
    stage_A(y0 + 1, 2);
    stage_A(y0 + 2, 3);
    stage_B(0, 0);
    CP_COMMIT_WAIT();
    __syncthreads();

    for (int ky = 0; ky < 3; ky++) {
        // prefetch next B into the other buffer during compute
        if (ky < 2) { stage_B(ky + 1, (ky + 1) & 1); CP_COMMIT(); }

        const uint32_t as0 = sbase + (ky)     * SA_SLOT;   // row r=0 uses y0-1+ky
        const uint32_t as1 = sbase + (ky + 1) * SA_SLOT;   // row r=1 uses y0+ky
        const uint32_t bbase = sbase + SB_OFF + (ky & 1) * SB_BUF;

        #pragma unroll
        for (int kx = 0; kx < 3; kx++) {
            const int h = m0 + rA + kx;
            const int hx = h & 7;
            const uint32_t a0row = as0 + h * 128;
            const uint32_t a1row = as1 + h * 128;
            const uint32_t bkx = bbase + kx * 8192;
            #pragma unroll
            for (int kc = 0; kc < 4; kc++) {
                const uint32_t koff = (uint32_t)((kc * 2 + khA) ^ hx) << 4;
                uint32_t bf[16];
                #pragma unroll
                for (int j = 0; j < 4; j++) {
                    int n = j * 16 + qn * 8 + rn;
                    ldsm4(&bf[j * 4], bkx + n * 128 + (((uint32_t)((kc * 2 + khB) ^ (n & 7))) << 4));
                }
                uint32_t ah0[4], ah1[4];
                ldsm4(ah0, a0row + koff);
                ldsm4(ah1, a1row + koff);
                #pragma unroll
                for (int j = 0; j < 4; j++) {
                    mma16816(acc[0][2 * j],     ah0, bf[4 * j],     bf[4 * j + 1]);
                    mma16816(acc[0][2 * j + 1], ah0, bf[4 * j + 2], bf[4 * j + 3]);
                    mma16816(acc[1][2 * j],     ah1, bf[4 * j],     bf[4 * j + 1]);
                    mma16816(acc[1][2 * j + 1], ah1, bf[4 * j + 2], bf[4 * j + 3]);
                }
            }
        }
        if (ky < 2) {
            CP_WAIT0();          // B(ky+1) surely in flight-complete by now
            __syncthreads();     // visibility + protects buf reuse next iter
        }
    }

    // ---- epilogue ----
    const int r0 = lane >> 2;
    const int cp = (lane & 3) * 2;
    #pragma unroll
    for (int r = 0; r < 2; r++) {
        const int y = y0 + r;
        #pragma unroll
        for (int j = 0; j < 8; j++) {
            const int ch = j * 8 + cp;
            const float b0 = ab[b * C + ch];
            const float b1 = ab[b * C + ch + 1];
            #pragma unroll
            for (int rr = 0; rr < 2; rr++) {
                const int x = m0 + r0 + rr * 8;
                float v0 = acc[r][j][rr * 2 + 0] + b0;
                float v1 = acc[r][j][rr * 2 + 1] + b1;
                if (final_layer) {
                    out_f32[((size_t)(b * C + ch) * H + y) * W + x]     = v0;
                    out_f32[((size_t)(b * C + ch + 1) * H + y) * W + x] = v1;
                } else {
                    __half2 p = __floats2half2_rn(v0, v1);
                    size_t base = (((size_t)b * H + y) * W + x) * C + ch;
                    *(uint32_t*)(out_a + base) = *(uint32_t*)&p;
                }
            }
        }
    }
}

// ---------------- launch ----------------
extern "C" void kernel_launch(void* const* d_in, const int* in_sizes, int n_in,
                              void* d_out, int out_size) {
    (void)in_sizes; (void)n_in; (void)out_size;
    const float* x       = (const float*)d_in[0];
    const float* w_ctrl1 = (const float*)d_in[1];
    const float* w_ctrl2 = (const float*)d_in[2];
    const float* weight1 = (const float*)d_in[3];
    const float* weight2 = (const float*)d_in[4];
    const float* weight3 = (const float*)d_in[5];
    const float* bias1   = (const float*)d_in[6];
    const float* bias2   = (const float*)d_in[7];
    const float* bias3   = (const float*)d_in[8];
    float* out = (float*)d_out;

    __half *wB, *a0, *a1;
    float* ab;
    cudaGetSymbolAddress((void**)&wB, g_wB);
    cudaGetSymbolAddress((void**)&ab, g_ab);
    cudaGetSymbolAddress((void**)&a0, g_a0);
    cudaGetSymbolAddress((void**)&a1, g_a1);

    cudaFuncSetAttribute(conv_mma_kernel, cudaFuncAttributeMaxDynamicSharedMemorySize, SMEM_TOTAL);

    xsplit_kernel<<<dim3(H, BS), 256>>>(x, a0);
    pool2_kernel<<<4, 256>>>();
    ctrl_kernel<<<1, 256>>>(w_ctrl1, w_ctrl2, bias1, bias2, bias3);
    mixsplit_kernel<<<dim3(BS, 3), 256>>>(weight1, weight2, weight3);

    const size_t wlayer = (size_t)BS * 3 * 3 * 4096;
    dim3 grid(H / 2, BS);
    conv_mma_kernel<<<grid, 256, SMEM_TOTAL>>>(a0, wB + 0 * wlayer, ab + 0 * BS * C,
                                               nullptr, a1, 0);
    conv_mma_kernel<<<grid, 256, SMEM_TOTAL>>>(a1, wB + 1 * wlayer, ab + 1 * BS * C,
                                               nullptr, a0, 0);
    conv_mma_kernel<<<grid, 256, SMEM_TOTAL>>>(a0, wB + 2 * wlayer, ab + 2 * BS * C,
                                               out, nullptr, 1);
}

// round 11
// speedup vs baseline: 1.3155x; 1.3155x over previous
#include <cuda_runtime.h>
#include <cuda_fp16.h>
#include <cstdint>
#include <math.h>

#define BS 16
#define C  64
#define H  128
#define W  128
#define EXP 4
#define HID 16

// ---------------- static device scratch ----------------
__device__ float g_rowsum[BS * C * H];     // [b][c][y]
__device__ float g_pooled[BS * C];
__device__ float g_coeff[BS * C * EXP];
__device__ float g_ab[3 * BS * C];
// pre-mixed fp16 weights: [layer][b][ky][kx][o=64][ci=64]
__device__ __align__(16) __half g_wB[3 * BS * 3 * 3 * 64 * 64];
// NHWC fp16 ping-pong activation planes: [b][y][x][ci]
__device__ __align__(16) __half g_a0[BS * H * W * C];
__device__ __align__(16) __half g_a1[BS * H * W * C];

// ---------------- helpers ----------------
__device__ __forceinline__ uint32_t smem_u32(const void* p) {
    uint32_t a;
    asm("{ .reg .u64 t; cvta.to.shared.u64 t, %1; cvt.u32.u64 %0, t; }" : "=r"(a) : "l"(p));
    return a;
}
__device__ __forceinline__ void ldsm4(uint32_t* r, uint32_t addr) {
    asm volatile("ldmatrix.sync.aligned.m8n8.x4.shared.b16 {%0,%1,%2,%3}, [%4];"
        : "=r"(r[0]), "=r"(r[1]), "=r"(r[2]), "=r"(r[3]) : "r"(addr));
}
__device__ __forceinline__ void mma16816(float* c, const uint32_t* a, uint32_t b0, uint32_t b1) {
    asm volatile("mma.sync.aligned.m16n8k16.row.col.f32.f16.f16.f32 "
        "{%0,%1,%2,%3}, {%4,%5,%6,%7}, {%8,%9}, {%0,%1,%2,%3};"
        : "+f"(c[0]), "+f"(c[1]), "+f"(c[2]), "+f"(c[3])
        : "r"(a[0]), "r"(a[1]), "r"(a[2]), "r"(a[3]), "r"(b0), "r"(b1));
}
#define CP16(dst, src, sz) \
    asm volatile("cp.async.cg.shared.global [%0], [%1], 16, %2;" \
        :: "r"(dst), "l"(src), "r"(sz) : "memory")
#define CP_COMMIT() \
    asm volatile("cp.async.commit_group;" ::: "memory")
#define CP_WAIT0() \
    asm volatile("cp.async.wait_group 0;" ::: "memory")
#define CP_COMMIT_WAIT() \
    asm volatile("cp.async.commit_group;\n\tcp.async.wait_group 0;" ::: "memory")

// ---------------- kernel D: NCHW fp32 -> NHWC fp16 (+ per-row channel sums) ----------------
__global__ void xsplit_kernel(const float* __restrict__ x, __half* __restrict__ oh) {
    int y = blockIdx.x, b = blockIdx.y;
    __shared__ float sm[64][129];
    for (int i = threadIdx.x; i < 64 * 128; i += 256) {
        int ci = i >> 7, xx = i & 127;
        sm[ci][xx] = x[(((size_t)b * C + ci) * H + y) * W + xx];
    }
    __syncthreads();
    {
        int c = threadIdx.x >> 2, q = threadIdx.x & 3;
        float s = 0.f;
        #pragma unroll
        for (int i = 0; i < 32; i++) s += sm[c][q * 32 + i];
        s += __shfl_xor_sync(0xFFFFFFFF, s, 1);
        s += __shfl_xor_sync(0xFFFFFFFF, s, 2);
        if (q == 0) g_rowsum[((size_t)b * C + c) * H + y] = s;
    }
    int xx = threadIdx.x & 127;
    int half_ = threadIdx.x >> 7;
    size_t base = (((size_t)b * H + y) * W + xx) * C + half_ * 32;
    uint32_t hb[16];
    #pragma unroll
    for (int c = 0; c < 32; c += 2) {
        __half2 p = __floats2half2_rn(sm[half_ * 32 + c][xx], sm[half_ * 32 + c + 1][xx]);
        hb[c >> 1] = *(uint32_t*)&p;
    }
    #pragma unroll
    for (int q = 0; q < 4; q++)
        ((uint4*)(oh + base))[q] = ((uint4*)hb)[q];
}

// ---------------- kernel A2: reduce row sums -> pooled mean ----------------
__global__ void pool2_kernel() {
    int bc = blockIdx.x * 256 + threadIdx.x;
    if (bc >= BS * C) return;
    const float4* p = (const float4*)&g_rowsum[(size_t)bc * H];
    float s = 0.f;
    #pragma unroll
    for (int i = 0; i < H / 4; i++) {
        float4 v = p[i];
        s += (v.x + v.y) + (v.z + v.w);
    }
    g_pooled[bc] = s * (1.0f / (H * W));
}

// ---------------- kernel B: control MLP + softmax + bias mixing ----------------
__global__ void ctrl_kernel(const float* __restrict__ w1, const float* __restrict__ w2,
                            const float* __restrict__ b1, const float* __restrict__ b2,
                            const float* __restrict__ b3) {
    __shared__ float sp[BS * C];
    __shared__ float sh[BS * HID];
    __shared__ float sl[BS * EXP * C];
    int t = threadIdx.x;
    for (int i = t; i < BS * C; i += 256) sp[i] = g_pooled[i];
    __syncthreads();
    {
        int b = t / HID, hh = t % HID;
        float s = 0.f;
        #pragma unroll 8
        for (int c = 0; c < C; c++) s += sp[b * C + c] * w1[hh * C + c];
        sh[b * HID + hh] = fmaxf(s, 0.f);
    }
    __syncthreads();
    for (int b = 0; b < BS; b++) {
        float s = 0.f;
        #pragma unroll
        for (int h = 0; h < HID; h++) s += sh[b * HID + h] * w2[t * HID + h];
        sl[b * (EXP * C) + t] = s;
    }
    __syncthreads();
    for (int g = t; g < BS * C; g += 256) {
        int b = g / C, c = g % C;
        float v[EXP];
        float mx = -1e30f;
        #pragma unroll
        for (int e = 0; e < EXP; e++) {
            v[e] = sl[b * (EXP * C) + c * EXP + e] * (1.0f / 30.0f);
            mx = fmaxf(mx, v[e]);
        }
        float den = 0.f;
        #pragma unroll
        for (int e = 0; e < EXP; e++) { v[e] = expf(v[e] - mx); den += v[e]; }
        float inv = 1.0f / den;
        #pragma unroll
        for (int e = 0; e < EXP; e++) g_coeff[g * EXP + e] = v[e] * inv;
    }
    __syncthreads();
    for (int g = t; g < BS * C; g += 256) {
        int c = g % C;
        float c0 = g_coeff[g * EXP + 0], c1 = g_coeff[g * EXP + 1];
        float c2 = g_coeff[g * EXP + 2], c3 = g_coeff[g * EXP + 3];
        g_ab[0 * BS * C + g] = c0 * b1[c] + c1 * b1[C + c] + c2 * b1[2 * C + c] + c3 * b1[3 * C + c];
        g_ab[1 * BS * C + g] = c0 * b2[c] + c1 * b2[C + c] + c2 * b2[2 * C + c] + c3 * b2[3 * C + c];
        g_ab[2 * BS * C + g] = c0 * b3[c] + c1 * b3[C + c] + c2 * b3[2 * C + c] + c3 * b3[3 * C + c];
    }
}

// ---------------- kernel C: mix weights -> fp16 (one element/thread, write-coalesced) ----------------
__global__ void mixw2_kernel(const float* __restrict__ W1, const float* __restrict__ W2,
                             const float* __restrict__ W3) {
    const int layer = blockIdx.y;
    const float* Wt = (layer == 0) ? W1 : (layer == 1) ? W2 : W3;
    const int e = blockIdx.x * 256 + threadIdx.x;     // 0 .. 589823
    const int ci = e & 63;
    const int o  = (e >> 6) & 63;
    const int t  = e >> 12;                           // 0 .. 143  (= b*9 + pk)
    const int pk = t % 9;
    const int b  = t / 9;
    const float* cf = &g_coeff[(b * C + o) * EXP];
    const size_t eb = (size_t)C * C * 9;
    const size_t w0 = (((size_t)o) * C + ci) * 9 + pk;
    float v = cf[0] * Wt[w0] + cf[1] * Wt[eb + w0]
            + cf[2] * Wt[2 * eb + w0] + cf[3] * Wt[3 * eb + w0];
    g_wB[(((size_t)(layer * BS + b) * 9 + pk) * 4096) + o * 64 + ci] = __float2half_rn(v);
}

// ---------------- kernel E: mma.sync fp16 conv, 4-slot A prologue ----------------
#define SA_SLOT 16640
#define SB_OFF  66560
#define SB_BUF  24576
#define SMEM_TOTAL (SB_OFF + 2 * SB_BUF)

__global__ void __launch_bounds__(256, 2)
conv_mma_kernel(const __half* __restrict__ in_a,
                const __half* __restrict__ wb,
                const float* __restrict__ ab,
                float* __restrict__ out_f32,
                __half* __restrict__ out_a,
                int final_layer) {
    extern __shared__ __align__(16) unsigned char smem[];
    const uint32_t sbase = smem_u32(smem);
    const int tid  = threadIdx.x;
    const int y0   = blockIdx.x * 2;
    const int b    = blockIdx.y;
    const int lane = tid & 31;
    const int w    = tid >> 5;
    const int m0   = w * 16;

    const int rA  = lane & 15;
    const int khA = lane >> 4;
    const int rn  = lane & 7;
    const int khB = (lane >> 3) & 1;
    const int qn  = lane >> 4;

    float acc[2][8][4];
    #pragma unroll
    for (int r = 0; r < 2; r++)
        #pragma unroll
        for (int j = 0; j < 8; j++)
            #pragma unroll
            for (int q = 0; q < 4; q++) acc[r][j][q] = 0.f;

    const __half* wbb = wb + (size_t)b * (3 * 3 * 4096);

    auto stage_A = [&](int gy, int slot) {
        const int gy_ok = (gy >= 0 && gy < H);
        const size_t rowbase = ((size_t)(b * H + (gy_ok ? gy : 0)) * W) * C;
        const uint32_t slotbase = sbase + slot * SA_SLOT;
        for (int i = tid; i < 1040; i += 256) {
            int px = i >> 3, c = i & 7;
            int gx = px - 1;
            int ok = gy_ok && (gx >= 0) && (gx < W);
            const __half* sp = in_a + rowbase + (size_t)(ok ? gx : 0) * C + c * 8;
            uint32_t dst = slotbase + px * 128 + (((uint32_t)(c ^ (px & 7))) << 4);
            CP16(dst, sp, ok ? 16 : 0);
        }
    };
    auto stage_B = [&](int ky, int buf) {
        const __half* wk = wbb + (size_t)ky * (3 * 4096);
        for (int i = tid; i < 1536; i += 256) {
            int c = i & 7;
            int n = (i >> 3) & 63;
            int kx = i >> 9;
            const __half* sp = wk + (size_t)kx * 4096 + n * 64 + c * 8;
            uint32_t dst = sbase + SB_OFF + buf * SB_BUF + kx * 8192 + n * 128
                           + (((uint32_t)(c ^ (n & 7))) << 4);
            CP16(dst, sp, 16);
        }
    };

    stage_A(y0 - 1, 0);
    stage_A(y0,     1);
    stage_A(y0 + 1, 2);
    stage_A(y0 + 2, 3);
    stage_B(0, 0);
    CP_COMMIT_WAIT();
    __syncthreads();

    for (int ky = 0; ky < 3; ky++) {
        if (ky < 2) { stage_B(ky + 1, (ky + 1) & 1); CP_COMMIT(); }

        const uint32_t as0 = sbase + (ky)     * SA_SLOT;
        const uint32_t as1 = sbase + (ky + 1) * SA_SLOT;
        const uint32_t bbase = sbase + SB_OFF + (ky & 1) * SB_BUF;

        #pragma unroll
        for (int kx = 0; kx < 3; kx++) {
            const int h = m0 + rA + kx;
            const int hx = h & 7;
            const uint32_t a0row = as0 + h * 128;
            const uint32_t a1row = as1 + h * 128;
            const uint32_t bkx = bbase + kx * 8192;
            #pragma unroll
            for (int kc = 0; kc < 4; kc++) {
                const uint32_t koff = (uint32_t)((kc * 2 + khA) ^ hx) << 4;
                uint32_t bf[16];
                #pragma unroll
                for (int j = 0; j < 4; j++) {
                    int n = j * 16 + qn * 8 + rn;
                    ldsm4(&bf[j * 4], bkx + n * 128 + (((uint32_t)((kc * 2 + khB) ^ (n & 7))) << 4));
                }
                uint32_t ah0[4], ah1[4];
                ldsm4(ah0, a0row + koff);
                ldsm4(ah1, a1row + koff);
                #pragma unroll
                for (int j = 0; j < 4; j++) {
                    mma16816(acc[0][2 * j],     ah0, bf[4 * j],     bf[4 * j + 1]);
                    mma16816(acc[0][2 * j + 1], ah0, bf[4 * j + 2], bf[4 * j + 3]);
                    mma16816(acc[1][2 * j],     ah1, bf[4 * j],     bf[4 * j + 1]);
                    mma16816(acc[1][2 * j + 1], ah1, bf[4 * j + 2], bf[4 * j + 3]);
                }
            }
        }
        if (ky < 2) {
            CP_WAIT0();
            __syncthreads();
        }
    }

    const int r0 = lane >> 2;
    const int cp = (lane & 3) * 2;
    #pragma unroll
    for (int r = 0; r < 2; r++) {
        const int y = y0 + r;
        #pragma unroll
        for (int j = 0; j < 8; j++) {
            const int ch = j * 8 + cp;
            const float b0 = ab[b * C + ch];
            const float b1 = ab[b * C + ch + 1];
            #pragma unroll
            for (int rr = 0; rr < 2; rr++) {
                const int x = m0 + r0 + rr * 8;
                float v0 = acc[r][j][rr * 2 + 0] + b0;
                float v1 = acc[r][j][rr * 2 + 1] + b1;
                if (final_layer) {
                    out_f32[((size_t)(b * C + ch) * H + y) * W + x]     = v0;
                    out_f32[((size_t)(b * C + ch + 1) * H + y) * W + x] = v1;
                } else {
                    __half2 p = __floats2half2_rn(v0, v1);
                    size_t base = (((size_t)b * H + y) * W + x) * C + ch;
                    *(uint32_t*)(out_a + base) = *(uint32_t*)&p;
                }
            }
        }
    }
}

// ---------------- launch ----------------
extern "C" void kernel_launch(void* const* d_in, const int* in_sizes, int n_in,
                              void* d_out, int out_size) {
    (void)in_sizes; (void)n_in; (void)out_size;
    const float* x       = (const float*)d_in[0];
    const float* w_ctrl1 = (const float*)d_in[1];
    const float* w_ctrl2 = (const float*)d_in[2];
    const float* weight1 = (const float*)d_in[3];
    const float* weight2 = (const float*)d_in[4];
    const float* weight3 = (const float*)d_in[5];
    const float* bias1   = (const float*)d_in[6];
    const float* bias2   = (const float*)d_in[7];
    const float* bias3   = (const float*)d_in[8];
    float* out = (float*)d_out;

    __half *wB, *a0, *a1;
    float* ab;
    cudaGetSymbolAddress((void**)&wB, g_wB);
    cudaGetSymbolAddress((void**)&ab, g_ab);
    cudaGetSymbolAddress((void**)&a0, g_a0);
    cudaGetSymbolAddress((void**)&a1, g_a1);

    cudaFuncSetAttribute(conv_mma_kernel, cudaFuncAttributeMaxDynamicSharedMemorySize, SMEM_TOTAL);

    xsplit_kernel<<<dim3(H, BS), 256>>>(x, a0);
    pool2_kernel<<<4, 256>>>();
    ctrl_kernel<<<1, 256>>>(w_ctrl1, w_ctrl2, bias1, bias2, bias3);
    mixw2_kernel<<<dim3(2304, 3), 256>>>(weight1, weight2, weight3);

    const size_t wlayer = (size_t)BS * 3 * 3 * 4096;
    dim3 grid(H / 2, BS);
    conv_mma_kernel<<<grid, 256, SMEM_TOTAL>>>(a0, wB + 0 * wlayer, ab + 0 * BS * C,
                                               nullptr, a1, 0);
    conv_mma_kernel<<<grid, 256, SMEM_TOTAL>>>(a1, wB + 1 * wlayer, ab + 1 * BS * C,
                                               nullptr, a0, 0);
    conv_mma_kernel<<<grid, 256, SMEM_TOTAL>>>(a0, wB + 2 * wlayer, ab + 2 * BS * C,
                                               out, nullptr, 1);
}

// round 12
// speedup vs baseline: 1.3731x; 1.0438x over previous
#include <cuda_runtime.h>
#include <cuda_fp16.h>
#include <cstdint>
#include <math.h>

#define BS 16
#define C  64
#define H  128
#define W  128
#define EXP 4
#define HID 16

// ---------------- static device scratch ----------------
__device__ float g_rowsum[BS * C * H];     // [b][c][y]
__device__ float g_pooled[BS * C];
__device__ float g_coeff[BS * C * EXP];
__device__ float g_ab[3 * BS * C];
// pre-mixed fp16 weights: [layer][b][ky][kx][o=64][ci=64]
__device__ __align__(16) __half g_wB[3 * BS * 3 * 3 * 64 * 64];
// NHWC fp16 ping-pong activation planes: [b][y][x][ci]
__device__ __align__(16) __half g_a0[BS * H * W * C];
__device__ __align__(16) __half g_a1[BS * H * W * C];

// ---------------- helpers ----------------
__device__ __forceinline__ uint32_t smem_u32(const void* p) {
    uint32_t a;
    asm("{ .reg .u64 t; cvta.to.shared.u64 t, %1; cvt.u32.u64 %0, t; }" : "=r"(a) : "l"(p));
    return a;
}
__device__ __forceinline__ void ldsm4(uint32_t* r, uint32_t addr) {
    asm volatile("ldmatrix.sync.aligned.m8n8.x4.shared.b16 {%0,%1,%2,%3}, [%4];"
        : "=r"(r[0]), "=r"(r[1]), "=r"(r[2]), "=r"(r[3]) : "r"(addr));
}
__device__ __forceinline__ void mma16816(float* c, const uint32_t* a, uint32_t b0, uint32_t b1) {
    asm volatile("mma.sync.aligned.m16n8k16.row.col.f32.f16.f16.f32 "
        "{%0,%1,%2,%3}, {%4,%5,%6,%7}, {%8,%9}, {%0,%1,%2,%3};"
        : "+f"(c[0]), "+f"(c[1]), "+f"(c[2]), "+f"(c[3])
        : "r"(a[0]), "r"(a[1]), "r"(a[2]), "r"(a[3]), "r"(b0), "r"(b1));
}
#define CP16(dst, src, sz) \
    asm volatile("cp.async.cg.shared.global [%0], [%1], 16, %2;" \
        :: "r"(dst), "l"(src), "r"(sz) : "memory")
#define CP_COMMIT() \
    asm volatile("cp.async.commit_group;" ::: "memory")
#define CP_WAIT0() \
    asm volatile("cp.async.wait_group 0;" ::: "memory")
#define CP_COMMIT_WAIT() \
    asm volatile("cp.async.commit_group;\n\tcp.async.wait_group 0;" ::: "memory")

// ---------------- kernel D: NCHW fp32 -> NHWC fp16 (+ per-row channel sums) ----------------
__global__ void xsplit_kernel(const float* __restrict__ x, __half* __restrict__ oh) {
    int y = blockIdx.x, b = blockIdx.y;
    __shared__ float sm[64][129];
    for (int i = threadIdx.x; i < 64 * 128; i += 256) {
        int ci = i >> 7, xx = i & 127;
        sm[ci][xx] = x[(((size_t)b * C + ci) * H + y) * W + xx];
    }
    __syncthreads();
    // per-row channel sums: 4 threads per channel
    {
        int c = threadIdx.x >> 2, q = threadIdx.x & 3;
        float s = 0.f;
        #pragma unroll
        for (int i = 0; i < 32; i++) s += sm[c][q * 32 + i];
        s += __shfl_xor_sync(0xFFFFFFFF, s, 1);
        s += __shfl_xor_sync(0xFFFFFFFF, s, 2);
        if (q == 0) g_rowsum[((size_t)b * C + c) * H + y] = s;
    }
    // write NHWC fp16, fully coalesced: warp covers 4 pixels x full C = 4x128B contiguous
    const int c8 = threadIdx.x & 7;        // 16B chunk within the 128B pixel
    const int xl = threadIdx.x >> 3;       // pixel-within-group 0..31
    const size_t rowout = ((size_t)b * H + y) * W;
    #pragma unroll
    for (int it = 0; it < 4; it++) {
        const int xx = it * 32 + xl;
        uint32_t hb[4];
        #pragma unroll
        for (int k = 0; k < 8; k += 2) {
            __half2 p = __floats2half2_rn(sm[c8 * 8 + k][xx], sm[c8 * 8 + k + 1][xx]);
            hb[k >> 1] = *(uint32_t*)&p;
        }
        *(uint4*)(oh + (rowout + xx) * C + c8 * 8) = *(uint4*)hb;
    }
}

// ---------------- kernel A2: reduce row sums -> pooled mean (warp per bc) ----------------
__global__ void pool2_kernel() {
    const int w = threadIdx.x >> 5, lane = threadIdx.x & 31;
    const int bc = blockIdx.x * 8 + w;                 // 32 blocks x 8 warps = 1024
    float4 v = ((const float4*)&g_rowsum[(size_t)bc * H])[lane];
    float s = (v.x + v.y) + (v.z + v.w);
    #pragma unroll
    for (int o = 16; o; o >>= 1) s += __shfl_xor_sync(0xFFFFFFFF, s, o);
    if (lane == 0) g_pooled[bc] = s * (1.0f / (H * W));
}

// ---------------- kernel B: control MLP + softmax + bias mixing ----------------
__global__ void ctrl_kernel(const float* __restrict__ w1, const float* __restrict__ w2,
                            const float* __restrict__ b1, const float* __restrict__ b2,
                            const float* __restrict__ b3) {
    __shared__ float sp[BS * C];
    __shared__ float sh[BS * HID];
    __shared__ float sl[BS * EXP * C];
    int t = threadIdx.x;
    for (int i = t; i < BS * C; i += 256) sp[i] = g_pooled[i];
    __syncthreads();
    {
        int b = t / HID, hh = t % HID;
        float s = 0.f;
        #pragma unroll 8
        for (int c = 0; c < C; c++) s += sp[b * C + c] * w1[hh * C + c];
        sh[b * HID + hh] = fmaxf(s, 0.f);
    }
    __syncthreads();
    for (int b = 0; b < BS; b++) {
        float s = 0.f;
        #pragma unroll
        for (int h = 0; h < HID; h++) s += sh[b * HID + h] * w2[t * HID + h];
        sl[b * (EXP * C) + t] = s;
    }
    __syncthreads();
    for (int g = t; g < BS * C; g += 256) {
        int b = g / C, c = g % C;
        float v[EXP];
        float mx = -1e30f;
        #pragma unroll
        for (int e = 0; e < EXP; e++) {
            v[e] = sl[b * (EXP * C) + c * EXP + e] * (1.0f / 30.0f);
            mx = fmaxf(mx, v[e]);
        }
        float den = 0.f;
        #pragma unroll
        for (int e = 0; e < EXP; e++) { v[e] = expf(v[e] - mx); den += v[e]; }
        float inv = 1.0f / den;
        #pragma unroll
        for (int e = 0; e < EXP; e++) g_coeff[g * EXP + e] = v[e] * inv;
    }
    __syncthreads();
    for (int g = t; g < BS * C; g += 256) {
        int c = g % C;
        float c0 = g_coeff[g * EXP + 0], c1 = g_coeff[g * EXP + 1];
        float c2 = g_coeff[g * EXP + 2], c3 = g_coeff[g * EXP + 3];
        g_ab[0 * BS * C + g] = c0 * b1[c] + c1 * b1[C + c] + c2 * b1[2 * C + c] + c3 * b1[3 * C + c];
        g_ab[1 * BS * C + g] = c0 * b2[c] + c1 * b2[C + c] + c2 * b2[2 * C + c] + c3 * b2[3 * C + c];
        g_ab[2 * BS * C + g] = c0 * b3[c] + c1 * b3[C + c] + c2 * b3[2 * C + c] + c3 * b3[3 * C + c];
    }
}

// ---------------- kernel C: mix weights -> fp16 (one element/thread, write-coalesced) ----------------
__global__ void mixw2_kernel(const float* __restrict__ W1, const float* __restrict__ W2,
                             const float* __restrict__ W3) {
    const int layer = blockIdx.y;
    const float* Wt = (layer == 0) ? W1 : (layer == 1) ? W2 : W3;
    const int e = blockIdx.x * 256 + threadIdx.x;     // 0 .. 589823
    const int ci = e & 63;
    const int o  = (e >> 6) & 63;
    const int t  = e >> 12;                           // 0 .. 143  (= b*9 + pk)
    const int pk = t % 9;
    const int b  = t / 9;
    const float* cf = &g_coeff[(b * C + o) * EXP];
    const size_t eb = (size_t)C * C * 9;
    const size_t w0 = (((size_t)o) * C + ci) * 9 + pk;
    float v = cf[0] * Wt[w0] + cf[1] * Wt[eb + w0]
            + cf[2] * Wt[2 * eb + w0] + cf[3] * Wt[3 * eb + w0];
    g_wB[(((size_t)(layer * BS + b) * 9 + pk) * 4096) + o * 64 + ci] = __float2half_rn(v);
}

// ---------------- kernel E: mma.sync fp16 conv, 4-slot A prologue ----------------
#define SA_SLOT 16640
#define SB_OFF  66560
#define SB_BUF  24576
#define SMEM_TOTAL (SB_OFF + 2 * SB_BUF)

__global__ void __launch_bounds__(256, 2)
conv_mma_kernel(const __half* __restrict__ in_a,
                const __half* __restrict__ wb,
                const float* __restrict__ ab,
                float* __restrict__ out_f32,
                __half* __restrict__ out_a,
                int final_layer) {
    extern __shared__ __align__(16) unsigned char smem[];
    const uint32_t sbase = smem_u32(smem);
    const int tid  = threadIdx.x;
    const int y0   = blockIdx.x * 2;
    const int b    = blockIdx.y;
    const int lane = tid & 31;
    const int w    = tid >> 5;
    const int m0   = w * 16;

    const int rA  = lane & 15;
    const int khA = lane >> 4;
    const int rn  = lane & 7;
    const int khB = (lane >> 3) & 1;
    const int qn  = lane >> 4;

    float acc[2][8][4];
    #pragma unroll
    for (int r = 0; r < 2; r++)
        #pragma unroll
        for (int j = 0; j < 8; j++)
            #pragma unroll
            for (int q = 0; q < 4; q++) acc[r][j][q] = 0.f;

    const __half* wbb = wb + (size_t)b * (3 * 3 * 4096);

    auto stage_A = [&](int gy, int slot) {
        const int gy_ok = (gy >= 0 && gy < H);
        const size_t rowbase = ((size_t)(b * H + (gy_ok ? gy : 0)) * W) * C;
        const uint32_t slotbase = sbase + slot * SA_SLOT;
        for (int i = tid; i < 1040; i += 256) {
            int px = i >> 3, c = i & 7;
            int gx = px - 1;
            int ok = gy_ok && (gx >= 0) && (gx < W);
            const __half* sp = in_a + rowbase + (size_t)(ok ? gx : 0) * C + c * 8;
            uint32_t dst = slotbase + px * 128 + (((uint32_t)(c ^ (px & 7))) << 4);
            CP16(dst, sp, ok ? 16 : 0);
        }
    };
    auto stage_B = [&](int ky, int buf) {
        const __half* wk = wbb + (size_t)ky * (3 * 4096);
        for (int i = tid; i < 1536; i += 256) {
            int c = i & 7;
            int n = (i >> 3) & 63;
            int kx = i >> 9;
            const __half* sp = wk + (size_t)kx * 4096 + n * 64 + c * 8;
            uint32_t dst = sbase + SB_OFF + buf * SB_BUF + kx * 8192 + n * 128
                           + (((uint32_t)(c ^ (n & 7))) << 4);
            CP16(dst, sp, 16);
        }
    };

    stage_A(y0 - 1, 0);
    stage_A(y0,     1);
    stage_A(y0 + 1, 2);
    stage_A(y0 + 2, 3);
    stage_B(0, 0);
    CP_COMMIT_WAIT();
    __syncthreads();

    for (int ky = 0; ky < 3; ky++) {
        if (ky < 2) { stage_B(ky + 1, (ky + 1) & 1); CP_COMMIT(); }

        const uint32_t as0 = sbase + (ky)     * SA_SLOT;
        const uint32_t as1 = sbase + (ky + 1) * SA_SLOT;
        const uint32_t bbase = sbase + SB_OFF + (ky & 1) * SB_BUF;

        #pragma unroll
        for (int kx = 0; kx < 3; kx++) {
            const int h = m0 + rA + kx;
            const int hx = h & 7;
            const uint32_t a0row = as0 + h * 128;
            const uint32_t a1row = as1 + h * 128;
            const uint32_t bkx = bbase + kx * 8192;
            #pragma unroll
            for (int kc = 0; kc < 4; kc++) {
                const uint32_t koff = (uint32_t)((kc * 2 + khA) ^ hx) << 4;
                uint32_t bf[16];
                #pragma unroll
                for (int j = 0; j < 4; j++) {
                    int n = j * 16 + qn * 8 + rn;
                    ldsm4(&bf[j * 4], bkx + n * 128 + (((uint32_t)((kc * 2 + khB) ^ (n & 7))) << 4));
                }
                uint32_t ah0[4], ah1[4];
                ldsm4(ah0, a0row + koff);
                ldsm4(ah1, a1row + koff);
                #pragma unroll
                for (int j = 0; j < 4; j++) {
                    mma16816(acc[0][2 * j],     ah0, bf[4 * j],     bf[4 * j + 1]);
                    mma16816(acc[0][2 * j + 1], ah0, bf[4 * j + 2], bf[4 * j + 3]);
                    mma16816(acc[1][2 * j],     ah1, bf[4 * j],     bf[4 * j + 1]);
                    mma16816(acc[1][2 * j + 1], ah1, bf[4 * j + 2], bf[4 * j + 3]);
                }
            }
        }
        if (ky < 2) {
            CP_WAIT0();
            __syncthreads();
        }
    }

    const int r0 = lane >> 2;
    const int cp = (lane & 3) * 2;
    #pragma unroll
    for (int r = 0; r < 2; r++) {
        const int y = y0 + r;
        #pragma unroll
        for (int j = 0; j < 8; j++) {
            const int ch = j * 8 + cp;
            const float b0 = ab[b * C + ch];
            const float b1 = ab[b * C + ch + 1];
            #pragma unroll
            for (int rr = 0; rr < 2; rr++) {
                const int x = m0 + r0 + rr * 8;
                float v0 = acc[r][j][rr * 2 + 0] + b0;
                float v1 = acc[r][j][rr * 2 + 1] + b1;
                if (final_layer) {
                    out_f32[((size_t)(b * C + ch) * H + y) * W + x]     = v0;
                    out_f32[((size_t)(b * C + ch + 1) * H + y) * W + x] = v1;
                } else {
                    __half2 p = __floats2half2_rn(v0, v1);
                    size_t base = (((size_t)b * H + y) * W + x) * C + ch;
                    *(uint32_t*)(out_a + base) = *(uint32_t*)&p;
                }
            }
        }
    }
}

// ---------------- launch ----------------
extern "C" void kernel_launch(void* const* d_in, const int* in_sizes, int n_in,
                              void* d_out, int out_size) {
    (void)in_sizes; (void)n_in; (void)out_size;
    const float* x       = (const float*)d_in[0];
    const float* w_ctrl1 = (const float*)d_in[1];
    const float* w_ctrl2 = (const float*)d_in[2];
    const float* weight1 = (const float*)d_in[3];
    const float* weight2 = (const float*)d_in[4];
    const float* weight3 = (const float*)d_in[5];
    const float* bias1   = (const float*)d_in[6];
    const float* bias2   = (const float*)d_in[7];
    const float* bias3   = (const float*)d_in[8];
    float* out = (float*)d_out;

    __half *wB, *a0, *a1;
    float* ab;
    cudaGetSymbolAddress((void**)&wB, g_wB);
    cudaGetSymbolAddress((void**)&ab, g_ab);
    cudaGetSymbolAddress((void**)&a0, g_a0);
    cudaGetSymbolAddress((void**)&a1, g_a1);

    cudaFuncSetAttribute(conv_mma_kernel, cudaFuncAttributeMaxDynamicSharedMemorySize, SMEM_TOTAL);

    xsplit_kernel<<<dim3(H, BS), 256>>>(x, a0);
    pool2_kernel<<<32, 256>>>();
    ctrl_kernel<<<1, 256>>>(w_ctrl1, w_ctrl2, bias1, bias2, bias3);
    mixw2_kernel<<<dim3(2304, 3), 256>>>(weight1, weight2, weight3);

    const size_t wlayer = (size_t)BS * 3 * 3 * 4096;
    dim3 grid(H / 2, BS);
    conv_mma_kernel<<<grid, 256, SMEM_TOTAL>>>(a0, wB + 0 * wlayer, ab + 0 * BS * C,
                                               nullptr, a1, 0);
    conv_mma_kernel<<<grid, 256, SMEM_TOTAL>>>(a1, wB + 1 * wlayer, ab + 1 * BS * C,
                                               nullptr, a0, 0);
    conv_mma_kernel<<<grid, 256, SMEM_TOTAL>>>(a0, wB + 2 * wlayer, ab + 2 * BS * C,
                                               out, nullptr, 1);
}